// round 7
// baseline (speedup 1.0000x reference)
#include <cuda_runtime.h>
#include <cuda_bf16.h>
#include <cstdint>

#define NN   100000
#define TILE 128

// ---- scratch (allocation-free rule: __device__ globals) ----
__device__ float g_kyv[NN * 64];            // K1 output ky_v
__device__ float g_acc[NN * 64];            // scatter accumulator
__device__ float g_cnt[NN];                 // scatter counts
__device__ uint32_t g_Bhi[2][16][2048];     // prepacked W2 hi bf16 pairs [kid][c*4+g][col*32+m2]
__device__ uint32_t g_Blo[2][16][2048];     // prepacked W2 lo

// ============================================================================
// helpers
// ============================================================================
__device__ __forceinline__ uint32_t smem_u32(const void* p) {
    uint32_t a;
    asm("{ .reg .u64 t; cvta.to.shared.u64 t, %1; cvt.u32.u64 %0, t; }" : "=r"(a) : "l"(p));
    return a;
}
__device__ __forceinline__ void split_pack(float v0, float v1, uint32_t& hiw, uint32_t& low) {
    __nv_bfloat16 h0 = __float2bfloat16(v0), h1 = __float2bfloat16(v1);
    __nv_bfloat16 l0 = __float2bfloat16(v0 - __bfloat162float(h0));
    __nv_bfloat16 l1 = __float2bfloat16(v1 - __bfloat162float(h1));
    hiw = (uint32_t)__bfloat16_as_ushort(h0) | ((uint32_t)__bfloat16_as_ushort(h1) << 16);
    low = (uint32_t)__bfloat16_as_ushort(l0) | ((uint32_t)__bfloat16_as_ushort(l1) << 16);
}
__device__ __forceinline__ void lda4(uint32_t* r, uint32_t addr) {
    asm volatile("ldmatrix.sync.aligned.m8n8.x4.shared.b16 {%0,%1,%2,%3}, [%4];"
        : "=r"(r[0]), "=r"(r[1]), "=r"(r[2]), "=r"(r[3]) : "r"(addr));
}
__device__ __forceinline__ void ldb4(uint32_t* r, uint32_t addr) {
    asm volatile("ldmatrix.sync.aligned.m8n8.x4.shared.b16 {%0,%1,%2,%3}, [%4];"
        : "=r"(r[0]), "=r"(r[1]), "=r"(r[2]), "=r"(r[3]) : "r"(addr));
}
__device__ __forceinline__ void mma16816(float* c, const uint32_t* a, const uint32_t* b) {
    asm volatile("mma.sync.aligned.m16n8k16.row.col.f32.bf16.bf16.f32 "
        "{%0,%1,%2,%3}, {%4,%5,%6,%7}, {%8,%9}, {%0,%1,%2,%3};"
        : "+f"(c[0]), "+f"(c[1]), "+f"(c[2]), "+f"(c[3])
        : "r"(a[0]), "r"(a[1]), "r"(a[2]), "r"(a[3]), "r"(b[0]), "r"(b[1]));
}

// smem layout (bytes). A/B rows 144B (16B-aligned for ldmatrix; 144 mod 128 = 16
// -> conflict-free). After A-frag load, [0..36864) is dead: K2 stages v there
// (pitch 68 f32, 34816B). Tail reuses O_BHI for mW^T (pitch 68 f32, 17408B).
enum { O_AHI = 0,                       // H hi : 128 x 144 = 18432
       O_ALO = 18432,                   // H lo : 128 x 144
       O_BHI = 36864,                   // Bt hi:  64 x 144 = 9216
       O_BLO = 46080,                   // Bt lo:  64 x 144
       O_B2  = 55296,                   // b2 chunk: 256 f32
       SMEM_SZ = 56320 };

// ============================================================================
// prep: W2 -> bf16 hi/lo, ldmatrix tile layout [col][m2]. 32 blocks, ~5us.
// ============================================================================
__global__ __launch_bounds__(256)
void prep_kernel(const float* __restrict__ W2a, const float* __restrict__ W2b)
{
    const int b = blockIdx.x;              // 0..31
    const int k = b >> 4, t = b & 15;
    const int c = t >> 2, g = t & 3;
    const float* W2 = k ? W2b : W2a;
    const int tid = threadIdx.x;
    #pragma unroll
    for (int it = 0; it < 8; it++) {
        int p = tid + it * 256;            // 2048
        int col = p & 63, m2 = p >> 6;
        float w0 = W2[(size_t)(2 * m2)     * 1024 + c * 256 + g * 64 + col];
        float w1 = W2[(size_t)(2 * m2 + 1) * 1024 + c * 256 + g * 64 + col];
        uint32_t hi, lo;
        split_pack(w0, w1, hi, lo);
        g_Bhi[k][t][col * 32 + m2] = hi;
        g_Blo[k][t][col * 32 + m2] = lo;
    }
}

// ============================================================================
// Fused node kernel. A (H tile) frags loaded ONCE into registers; per gg:
// STS prefetched B, LDG-prefetch next B, 36 HMMA from regs+B smem, phase B in
// registers. K1 -> g_kyv (+zero acc/cnt). K2: v -> smem, then mix Linear tail.
// ============================================================================
template<int IS_K2>
__global__ __launch_bounds__(256, 2)
void node_kernel(const float* __restrict__ xin, const float* __restrict__ ea,
                 const float* __restrict__ W1, const float* __restrict__ b1,
                 const float* __restrict__ b2,
                 const float* __restrict__ mW, const float* __restrict__ mb,
                 float* __restrict__ out, int n)
{
    extern __shared__ __align__(16) char sm[];
    const uint32_t smb = smem_u32(sm);
    const int tid = threadIdx.x, wid = tid >> 5, lane = tid & 31;
    const int nb = blockIdx.x * TILE;

    // ---- stage A: h = relu(ea@W1+b1) hi/lo bf16, [node][m], row 144B ----
    {
        const int node = tid >> 1, mh = tid & 1;
        const bool ok = (nb + node) < n;
        float e0 = 0.f, e1 = 0.f, e2 = 0.f;
        if (ok) { const float* e = ea + (size_t)(nb + node) * 3; e0 = e[0]; e1 = e[1]; e2 = e[2]; }
        #pragma unroll
        for (int mm = 0; mm < 16; mm++) {
            int m = mh * 32 + mm * 2;
            float h0 = 0.f, h1 = 0.f;
            if (ok) {
                h0 = fmaxf(fmaf(e2, W1[128 + m],     fmaf(e1, W1[64 + m],     fmaf(e0, W1[m],     b1[m]))),     0.f);
                h1 = fmaxf(fmaf(e2, W1[128 + m + 1], fmaf(e1, W1[64 + m + 1], fmaf(e0, W1[m + 1], b1[m + 1]))), 0.f);
            }
            uint32_t hiw, low;
            split_pack(h0, h1, hiw, low);
            uint32_t off = (uint32_t)(node * 144 + m * 2);
            *(uint32_t*)(sm + O_AHI + off) = hiw;
            *(uint32_t*)(sm + O_ALO + off) = low;
        }
    }
    // ---- K1: zero scatter accumulators for this tile ----
    if (!IS_K2) {
        const float4 z4 = make_float4(0.f, 0.f, 0.f, 0.f);
        #pragma unroll
        for (int i = 0; i < 8; i++) {
            int idx4 = tid + i * 256;
            int node = idx4 >> 4;
            if (nb + node < n) ((float4*)g_acc)[(size_t)nb * 16 + idx4] = z4;
        }
        if (tid < TILE && nb + tid < n) g_cnt[nb + tid] = 0.f;
    }
    __syncthreads();                               // A staged

    // ---- load A fragments ONCE (loop-invariant across all 16 groups) ----
    const uint32_t aRow = (uint32_t)((wid * 16 + (lane & 15)) * 144 + ((lane >> 4) * 16));
    uint32_t ah[4][4], al[4][4];
    #pragma unroll
    for (int ks = 0; ks < 4; ks++) {
        lda4(ah[ks], smb + O_AHI + aRow + ks * 32);
        lda4(al[ks], smb + O_ALO + aRow + ks * 32);
    }
    __syncthreads();                               // A smem region now dead

    // x4 B addressing: lanes 16-31 take the next ct tile (+8 rows = +1152B)
    const uint32_t bRow4 = (uint32_t)((lane & 7) * 144 + (((lane >> 3) & 1) * 16)
                                      + ((lane >> 4) * 1152));
    const int r0   = wid * 16 + (lane >> 2);       // C frag rows r0, r0+8
    const int colq = 2 * (lane & 3);

    const int row0 = nb + r0, row1 = nb + r0 + 8;
    const bool v0 = row0 < n, v1 = row1 < n;
    const float* src = IS_K2 ? g_acc : xin;
    float inv0 = 1.f, inv1 = 1.f;
    if (IS_K2) {
        if (v0) inv0 = 1.0f / fmaxf(g_cnt[row0], 1.0f);
        if (v1) inv1 = 1.0f / fmaxf(g_cnt[row1], 1.0f);
    }

    // ---- prefetch first B tile into regs ----
    const int col_s = tid >> 3, m2s = (tid & 7) * 4;      // it=0 slot
    const int col_s2 = (tid + 256) >> 3;                  // it=1 slot
    uint4 pfh0 = ((const uint4*)g_Bhi[IS_K2][0])[tid];
    uint4 pfl0 = ((const uint4*)g_Blo[IS_K2][0])[tid];
    uint4 pfh1 = ((const uint4*)g_Bhi[IS_K2][0])[tid + 256];
    uint4 pfl1 = ((const uint4*)g_Blo[IS_K2][0])[tid + 256];

    for (int q = 0; q < 16; q++) {                 // q = c*4 + gg
        const int c = q >> 2, gg = q & 3;
        __syncthreads();                           // prior consumers of B done
        // ---- STS prefetched B tile ----
        *(uint4*)(sm + O_BHI + col_s  * 144 + m2s * 4) = pfh0;
        *(uint4*)(sm + O_BLO + col_s  * 144 + m2s * 4) = pfl0;
        *(uint4*)(sm + O_BHI + col_s2 * 144 + m2s * 4) = pfh1;
        *(uint4*)(sm + O_BLO + col_s2 * 144 + m2s * 4) = pfl1;
        if (gg == 0 && tid < 64)
            ((float4*)(sm + O_B2))[tid] = ((const float4*)(b2 + c * 256))[tid];
        // ---- LDG prefetch next tile (latency hidden behind MMAs) ----
        {
            int qn = (q + 1) & 15;
            pfh0 = ((const uint4*)g_Bhi[IS_K2][qn])[tid];
            pfl0 = ((const uint4*)g_Blo[IS_K2][qn])[tid];
            pfh1 = ((const uint4*)g_Bhi[IS_K2][qn])[tid + 256];
            pfl1 = ((const uint4*)g_Blo[IS_K2][qn])[tid + 256];
        }
        __syncthreads();                           // B ready

        // ---- HMMA: acc = Ah*Bh + Al*Bh + Ah*Bl (A frags in regs) ----
        float acc[8][4];
        #pragma unroll
        for (int ct = 0; ct < 8; ct++)
            #pragma unroll
            for (int p = 0; p < 4; p++) acc[ct][p] = 0.f;
        #pragma unroll
        for (int ks = 0; ks < 4; ks++) {
            uint32_t bh[8][2];
            #pragma unroll
            for (int c2 = 0; c2 < 4; c2++) {
                uint32_t bq[4];
                ldb4(bq, smb + O_BHI + (uint32_t)(c2 * 2304) + bRow4 + ks * 32);
                bh[2*c2][0] = bq[0]; bh[2*c2][1] = bq[1];
                bh[2*c2+1][0] = bq[2]; bh[2*c2+1][1] = bq[3];
            }
            #pragma unroll
            for (int ct = 0; ct < 8; ct++) mma16816(acc[ct], ah[ks], bh[ct]);
            #pragma unroll
            for (int ct = 0; ct < 8; ct++) mma16816(acc[ct], al[ks], bh[ct]);
            #pragma unroll
            for (int c2 = 0; c2 < 4; c2++) {
                uint32_t bq[4];
                ldb4(bq, smb + O_BLO + (uint32_t)(c2 * 2304) + bRow4 + ks * 32);
                uint32_t bl0[2] = {bq[0], bq[1]}, bl1[2] = {bq[2], bq[3]};
                mma16816(acc[2*c2],     ah[ks], bl0);
                mma16816(acc[2*c2 + 1], ah[ks], bl1);
            }
        }

        // ---- phase B (registers): kl = ct>>1, j = (ct&1)*8 + colq + {0,1} ----
        float4 x0 = make_float4(0.f, 0.f, 0.f, 0.f), x1 = x0;
        if (v0) x0 = *(const float4*)&src[(size_t)row0 * 64 + c * 16 + gg * 4];
        if (v1) x1 = *(const float4*)&src[(size_t)row1 * 64 + c * 16 + gg * 4];
        float xk0[4] = {x0.x, x0.y, x0.z, x0.w};
        float xk1[4] = {x1.x, x1.y, x1.z, x1.w};
        const float* b2s = (const float*)(sm + O_B2);
        float y[8] = {0.f, 0.f, 0.f, 0.f, 0.f, 0.f, 0.f, 0.f};
        #pragma unroll
        for (int ct = 0; ct < 8; ct++) {
            float2 bb = *(const float2*)&b2s[gg * 64 + ct * 8 + colq];
            int kl = ct >> 1, jb = (ct & 1) * 2;
            y[jb]     = fmaf(xk0[kl], acc[ct][0] + bb.x, y[jb]);
            y[jb + 1] = fmaf(xk0[kl], acc[ct][1] + bb.y, y[jb + 1]);
            y[4 + jb]     = fmaf(xk1[kl], acc[ct][2] + bb.x, y[4 + jb]);
            y[4 + jb + 1] = fmaf(xk1[kl], acc[ct][3] + bb.y, y[4 + jb + 1]);
        }
        // y holds partials for k = gg*4..gg*4+3; accumulate across gg via gmem/smem:
        if (!IS_K2) {
            // accumulate into registers across gg: use smem-free approach —
            // partial sums per gg are disjoint in k, so sum over gg needed.
            // We keep per-c accumulation in y across gg via static regs:
            // handled below with yacc.
        }
        // accumulate across the 4 gg of this c
        static_assert(true, "");
        {
            // persistent per-c accumulator
            // (declared outside gg loop in original; emulate via smem-free trick)
        }
        // --- fold into per-c accumulator ---
        if (gg == 0) {
            #pragma unroll
            for (int s = 0; s < 8; s++) acc[0][0] = acc[0][0];  // no-op
        }
        // store/accumulate
        if (!IS_K2) {
            if (gg == 0) {
                if (v0) { *(float2*)&g_kyv[(size_t)row0 * 64 + c * 16 + colq]     = make_float2(y[0], y[1]);
                          *(float2*)&g_kyv[(size_t)row0 * 64 + c * 16 + 8 + colq] = make_float2(y[2], y[3]); }
                if (v1) { *(float2*)&g_kyv[(size_t)row1 * 64 + c * 16 + colq]     = make_float2(y[4], y[5]);
                          *(float2*)&g_kyv[(size_t)row1 * 64 + c * 16 + 8 + colq] = make_float2(y[6], y[7]); }
            } else {
                if (v0) { float2* p0 = (float2*)&g_kyv[(size_t)row0 * 64 + c * 16 + colq];
                          float2* p1 = (float2*)&g_kyv[(size_t)row0 * 64 + c * 16 + 8 + colq];
                          float2 o0 = *p0, o1 = *p1;
                          *p0 = make_float2(o0.x + y[0], o0.y + y[1]);
                          *p1 = make_float2(o1.x + y[2], o1.y + y[3]); }
                if (v1) { float2* p0 = (float2*)&g_kyv[(size_t)row1 * 64 + c * 16 + colq];
                          float2* p1 = (float2*)&g_kyv[(size_t)row1 * 64 + c * 16 + 8 + colq];
                          float2 o0 = *p0, o1 = *p1;
                          *p0 = make_float2(o0.x + y[4], o0.y + y[5]);
                          *p1 = make_float2(o1.x + y[6], o1.y + y[7]); }
            }
        } else {
            // v staged in dead A region, pitch 68 floats (272B/row)
            char* vr0 = sm + r0 * 272 + (c * 16 + colq) * 4;
            char* vr1 = sm + (r0 + 8) * 272 + (c * 16 + colq) * 4;
            if (gg == 0) {
                *(float2*)vr0        = make_float2(y[0], y[1]);
                *(float2*)(vr0 + 32) = make_float2(y[2], y[3]);
                *(float2*)vr1        = make_float2(y[4], y[5]);
                *(float2*)(vr1 + 32) = make_float2(y[6], y[7]);
            } else {
                float2 a0 = *(float2*)vr0, a1 = *(float2*)(vr0 + 32);
                float2 a2 = *(float2*)vr1, a3 = *(float2*)(vr1 + 32);
                a0.x += y[0]; a0.y += y[1]; a1.x += y[2]; a1.y += y[3];
                a2.x += y[4]; a2.y += y[5]; a3.x += y[6]; a3.y += y[7];
                if (gg == 3) {
                    a0.x *= inv0; a0.y *= inv0; a1.x *= inv0; a1.y *= inv0;
                    a2.x *= inv1; a2.y *= inv1; a3.x *= inv1; a3.y *= inv1;
                }
                *(float2*)vr0        = a0;
                *(float2*)(vr0 + 32) = a1;
                *(float2*)vr1        = a2;
                *(float2*)(vr1 + 32) = a3;
            }
        }
    }

    // ---- K2 tail: out = v @ mW^T + mb.  v in smem [0..34816), mW^T -> O_BHI.
    if (IS_K2) {
        __syncthreads();                           // v writes + B reads done
        #pragma unroll
        for (int it = 0; it < 16; it++) {
            int p = tid + it * 256;                // 4096
            int j = p >> 6, i = p & 63;
            *(float*)(sm + O_BHI + (j * 68 + i) * 4) = mW[(size_t)i * 64 + j];
        }
        __syncthreads();
        const int node_b = tid >> 1, jh = tid & 1;
        if (nb + node_b < n) {
            float a[32];
            #pragma unroll
            for (int p = 0; p < 8; p++) {
                float4 m4 = ((const float4*)mb)[jh * 8 + p];
                a[p*4] = m4.x; a[p*4+1] = m4.y; a[p*4+2] = m4.z; a[p*4+3] = m4.w;
            }
            #pragma unroll 4
            for (int j = 0; j < 64; j++) {
                float vj = *(const float*)(sm + (node_b * 68 + j) * 4);
                #pragma unroll
                for (int p = 0; p < 8; p++) {
                    float4 w = *(const float4*)(sm + O_BHI + (j * 68 + jh * 32 + p * 4) * 4);
                    a[p*4]   = fmaf(vj, w.x, a[p*4]);
                    a[p*4+1] = fmaf(vj, w.y, a[p*4+1]);
                    a[p*4+2] = fmaf(vj, w.z, a[p*4+2]);
                    a[p*4+3] = fmaf(vj, w.w, a[p*4+3]);
                }
            }
            float* dst = &out[(size_t)(nb + node_b) * 64 + jh * 32];
            #pragma unroll
            for (int p = 0; p < 8; p++)
                ((float4*)dst)[p] = make_float4(a[p*4], a[p*4+1], a[p*4+2], a[p*4+3]);
        }
    }
}

// ============================================================================
// Edge scatter: acc[dst] += ky_v[src], cnt[dst] += 1.  float4 vector atomics.
// ============================================================================
__global__ __launch_bounds__(256)
void scatter_kernel(const int* __restrict__ ei, int n_edges)
{
    __shared__ int s_dst[256];
    __shared__ int s_src[256];
    const int tid  = threadIdx.x;
    const int base = blockIdx.x * 256;
    const int nE   = min(256, n_edges - base);
    if (nE <= 0) return;

    if (tid < nE) {
        s_dst[tid] = ei[base + tid];
        s_src[tid] = ei[n_edges + base + tid];
    }
    __syncthreads();

    const int w = tid >> 5, lane = tid & 31;
    const int half16 = lane >> 4, l16 = lane & 15;

    #pragma unroll 4
    for (int p = 0; p < 16; p++) {
        int le = w * 32 + p * 2 + half16;
        if (le < nE) {
            int src = s_src[le];
            int dst = s_dst[le];
            float4 v = *(const float4*)&g_kyv[(size_t)src * 64 + l16 * 4];
            atomicAdd((float4*)&g_acc[(size_t)dst * 64 + l16 * 4], v);
            if (l16 == 0) atomicAdd(&g_cnt[dst], 1.0f);
        }
    }
}

// ============================================================================
extern "C" void kernel_launch(void* const* d_in, const int* in_sizes, int n_in,
                              void* d_out, int out_size)
{
    const float* x    = (const float*)d_in[0];
    const float* ea   = (const float*)d_in[1];
    const int*   ei   = (const int*)  d_in[2];
    const float* k1W1 = (const float*)d_in[3];
    const float* k1b1 = (const float*)d_in[4];
    const float* k1W2 = (const float*)d_in[5];
    const float* k1b2 = (const float*)d_in[6];
    const float* k2W1 = (const float*)d_in[7];
    const float* k2b1 = (const float*)d_in[8];
    const float* k2W2 = (const float*)d_in[9];
    const float* k2b2 = (const float*)d_in[10];
    const float* mW   = (const float*)d_in[11];
    const float* mb   = (const float*)d_in[12];
    float* out = (float*)d_out;

    const int n = in_sizes[0] / 64;        // 100000
    const int e = in_sizes[2] / 2;         // 3200000

    cudaFuncSetAttribute(node_kernel<0>, cudaFuncAttributeMaxDynamicSharedMemorySize, SMEM_SZ);
    cudaFuncSetAttribute(node_kernel<1>, cudaFuncAttributeMaxDynamicSharedMemorySize, SMEM_SZ);

    const int node_blocks = (n + TILE - 1) / TILE;
    const int edge_blocks = (e + 255) / 256;

    prep_kernel<<<32, 256>>>(k1W2, k2W2);
    node_kernel<0><<<node_blocks, 256, SMEM_SZ>>>(x, ea, k1W1, k1b1, k1b2,
                                                  nullptr, nullptr, nullptr, n);
    scatter_kernel<<<edge_blocks, 256>>>(ei, e);
    node_kernel<1><<<node_blocks, 256, SMEM_SZ>>>(nullptr, ea, k2W1, k2b1, k2b2,
                                                  mW, mb, out, n);
}

// round 8
// speedup vs baseline: 1.0711x; 1.0711x over previous
#include <cuda_runtime.h>
#include <cuda_bf16.h>
#include <cstdint>

#define NN   100000
#define TILE 128

// ---- scratch (allocation-free rule: __device__ globals) ----
__device__ float g_kyv[NN * 64];            // K1 output ky_v
__device__ float g_acc[NN * 64];            // scatter accumulator
__device__ float g_cnt[NN];                 // scatter counts
__device__ uint32_t g_Bhi[2][16][2048];     // prepacked W2 hi bf16 pairs [kid][c*4+g][col*32+m2]
__device__ uint32_t g_Blo[2][16][2048];     // prepacked W2 lo

// ============================================================================
// helpers
// ============================================================================
__device__ __forceinline__ uint32_t smem_u32(const void* p) {
    uint32_t a;
    asm("{ .reg .u64 t; cvta.to.shared.u64 t, %1; cvt.u32.u64 %0, t; }" : "=r"(a) : "l"(p));
    return a;
}
__device__ __forceinline__ void split_pack(float v0, float v1, uint32_t& hiw, uint32_t& low) {
    __nv_bfloat16 h0 = __float2bfloat16(v0), h1 = __float2bfloat16(v1);
    __nv_bfloat16 l0 = __float2bfloat16(v0 - __bfloat162float(h0));
    __nv_bfloat16 l1 = __float2bfloat16(v1 - __bfloat162float(h1));
    hiw = (uint32_t)__bfloat16_as_ushort(h0) | ((uint32_t)__bfloat16_as_ushort(h1) << 16);
    low = (uint32_t)__bfloat16_as_ushort(l0) | ((uint32_t)__bfloat16_as_ushort(l1) << 16);
}
__device__ __forceinline__ void lda4(uint32_t* r, uint32_t addr) {
    asm volatile("ldmatrix.sync.aligned.m8n8.x4.shared.b16 {%0,%1,%2,%3}, [%4];"
        : "=r"(r[0]), "=r"(r[1]), "=r"(r[2]), "=r"(r[3]) : "r"(addr));
}
__device__ __forceinline__ void ldb4(uint32_t* r, uint32_t addr) {
    asm volatile("ldmatrix.sync.aligned.m8n8.x4.shared.b16 {%0,%1,%2,%3}, [%4];"
        : "=r"(r[0]), "=r"(r[1]), "=r"(r[2]), "=r"(r[3]) : "r"(addr));
}
__device__ __forceinline__ void mma16816(float* c, const uint32_t* a, const uint32_t* b) {
    asm volatile("mma.sync.aligned.m16n8k16.row.col.f32.bf16.bf16.f32 "
        "{%0,%1,%2,%3}, {%4,%5,%6,%7}, {%8,%9}, {%0,%1,%2,%3};"
        : "+f"(c[0]), "+f"(c[1]), "+f"(c[2]), "+f"(c[3])
        : "r"(a[0]), "r"(a[1]), "r"(a[2]), "r"(a[3]), "r"(b[0]), "r"(b[1]));
}
__device__ __forceinline__ void cp16(uint32_t d, const void* s) {
    asm volatile("cp.async.ca.shared.global [%0], [%1], 16;" :: "r"(d), "l"(s));
}
#define CP_COMMIT() asm volatile("cp.async.commit_group;" ::: "memory")
#define CP_WAIT0()  asm volatile("cp.async.wait_group 0;"  ::: "memory")

// smem layout (bytes). A/B rows 144B (16B-aligned for ldmatrix; 144 mod 128 = 16
// -> conflict-free). After A-frag load, [0..34816) is dead: K2 stages v there
// (pitch 68 f32). Tail reuses O_BUF for mW^T (pitch 68 f32, 17408B).
enum { O_AHI = 0,                       // H hi : 128 x 144 = 18432
       O_ALO = 18432,                   // H lo : 128 x 144
       O_BUF = 36864,                   // 2 x (Bt hi 9216 + Bt lo 9216) = 36864
       O_B2  = 73728,                   // full b2: 1024 f32 = 4096
       SMEM_SZ = 77824 };

// ============================================================================
// prep: W2 -> bf16 hi/lo, ldmatrix tile layout [col][m2]. 32 blocks, ~5us.
// ============================================================================
__global__ __launch_bounds__(256)
void prep_kernel(const float* __restrict__ W2a, const float* __restrict__ W2b)
{
    const int b = blockIdx.x;              // 0..31
    const int k = b >> 4, t = b & 15;
    const int c = t >> 2, g = t & 3;
    const float* W2 = k ? W2b : W2a;
    const int tid = threadIdx.x;
    #pragma unroll
    for (int it = 0; it < 8; it++) {
        int p = tid + it * 256;            // 2048
        int col = p & 63, m2 = p >> 6;
        float w0 = W2[(size_t)(2 * m2)     * 1024 + c * 256 + g * 64 + col];
        float w1 = W2[(size_t)(2 * m2 + 1) * 1024 + c * 256 + g * 64 + col];
        uint32_t hi, lo;
        split_pack(w0, w1, hi, lo);
        g_Bhi[k][t][col * 32 + m2] = hi;
        g_Blo[k][t][col * 32 + m2] = lo;
    }
}

// ============================================================================
// Fused node kernel. A (H tile) frags in registers (loaded once); B tiles
// double-buffered via cp.async (fetch q+1 overlaps MMA q, 1 barrier/gg);
// y accumulated in registers per c (written once). K1 -> g_kyv (+zero
// acc/cnt).  K2: v -> dead A smem region, then mix Linear tail.
// ============================================================================
template<int IS_K2>
__global__ __launch_bounds__(256, 2)
void node_kernel(const float* __restrict__ xin, const float* __restrict__ ea,
                 const float* __restrict__ W1, const float* __restrict__ b1,
                 const float* __restrict__ b2,
                 const float* __restrict__ mW, const float* __restrict__ mb,
                 float* __restrict__ out, int n)
{
    extern __shared__ __align__(16) char sm[];
    const uint32_t smb = smem_u32(sm);
    const int tid = threadIdx.x, wid = tid >> 5, lane = tid & 31;
    const int nb = blockIdx.x * TILE;

    // ---- stage A: h = relu(ea@W1+b1) hi/lo bf16, [node][m], row 144B ----
    {
        const int node = tid >> 1, mh = tid & 1;
        const bool ok = (nb + node) < n;
        float e0 = 0.f, e1 = 0.f, e2 = 0.f;
        if (ok) { const float* e = ea + (size_t)(nb + node) * 3; e0 = e[0]; e1 = e[1]; e2 = e[2]; }
        #pragma unroll
        for (int mm = 0; mm < 16; mm++) {
            int m = mh * 32 + mm * 2;
            float h0 = 0.f, h1 = 0.f;
            if (ok) {
                h0 = fmaxf(fmaf(e2, W1[128 + m],     fmaf(e1, W1[64 + m],     fmaf(e0, W1[m],     b1[m]))),     0.f);
                h1 = fmaxf(fmaf(e2, W1[128 + m + 1], fmaf(e1, W1[64 + m + 1], fmaf(e0, W1[m + 1], b1[m + 1]))), 0.f);
            }
            uint32_t hiw, low;
            split_pack(h0, h1, hiw, low);
            uint32_t off = (uint32_t)(node * 144 + m * 2);
            *(uint32_t*)(sm + O_AHI + off) = hiw;
            *(uint32_t*)(sm + O_ALO + off) = low;
        }
    }
    // ---- stage full b2 (1024 f32) once ----
    ((float4*)(sm + O_B2))[tid] = ((const float4*)b2)[tid];
    // ---- K1: zero scatter accumulators for this tile ----
    if (!IS_K2) {
        const float4 z4 = make_float4(0.f, 0.f, 0.f, 0.f);
        #pragma unroll
        for (int i = 0; i < 8; i++) {
            int idx4 = tid + i * 256;
            int node = idx4 >> 4;
            if (nb + node < n) ((float4*)g_acc)[(size_t)nb * 16 + idx4] = z4;
        }
        if (tid < TILE && nb + tid < n) g_cnt[nb + tid] = 0.f;
    }
    __syncthreads();                               // A + b2 staged

    // ---- load A fragments ONCE (loop-invariant across all 16 groups) ----
    const uint32_t aRow = (uint32_t)((wid * 16 + (lane & 15)) * 144 + ((lane >> 4) * 16));
    uint32_t ah[4][4], al[4][4];
    #pragma unroll
    for (int ks = 0; ks < 4; ks++) {
        lda4(ah[ks], smb + O_AHI + aRow + ks * 32);
        lda4(al[ks], smb + O_ALO + aRow + ks * 32);
    }

    // x4 B addressing: lanes 16-31 take the next ct tile (+8 rows = +1152B)
    const uint32_t bRow4 = (uint32_t)((lane & 7) * 144 + (((lane >> 3) & 1) * 16)
                                      + ((lane >> 4) * 1152));
    const int r0   = wid * 16 + (lane >> 2);       // C frag rows r0, r0+8
    const int colq = 2 * (lane & 3);

    const int row0 = nb + r0, row1 = nb + r0 + 8;
    const bool v0 = row0 < n, v1 = row1 < n;
    const float* src = IS_K2 ? g_acc : xin;
    float inv0 = 1.f, inv1 = 1.f;
    if (IS_K2) {
        if (v0) inv0 = 1.0f / fmaxf(g_cnt[row0], 1.0f);
        if (v1) inv1 = 1.0f / fmaxf(g_cnt[row1], 1.0f);
    }

    // per-thread cp.async slots (same tile mapping as prep layout)
    const uint32_t st_off0 = (uint32_t)((tid >> 3) * 144 + (tid & 7) * 16);
    const uint32_t st_off1 = (uint32_t)(((tid + 256) >> 3) * 144 + (tid & 7) * 16);

    // ---- prologue: stage tile q=0 into buf 0 ----
    {
        const char* sH = (const char*)g_Bhi[IS_K2][0];
        const char* sL = (const char*)g_Blo[IS_K2][0];
        uint32_t dH = smb + O_BUF;
        cp16(dH + st_off0,        sH + (size_t)tid * 16);
        cp16(dH + 9216 + st_off0, sL + (size_t)tid * 16);
        cp16(dH + st_off1,        sH + (size_t)(tid + 256) * 16);
        cp16(dH + 9216 + st_off1, sL + (size_t)(tid + 256) * 16);
        CP_COMMIT();
    }

    const float* b2s = (const float*)(sm + O_B2);

    for (int c = 0; c < 4; c++) {
        float y[8] = {0.f, 0.f, 0.f, 0.f, 0.f, 0.f, 0.f, 0.f};

        for (int gg = 0; gg < 4; gg++) {
            const int q = c * 4 + gg;
            CP_WAIT0();
            __syncthreads();                       // buf q ready; buf q+1 free
            if (q < 15) {                          // async-stage next tile
                const char* sH = (const char*)g_Bhi[IS_K2][q + 1];
                const char* sL = (const char*)g_Blo[IS_K2][q + 1];
                uint32_t dH = smb + O_BUF + ((q + 1) & 1) * 18432;
                cp16(dH + st_off0,        sH + (size_t)tid * 16);
                cp16(dH + 9216 + st_off0, sL + (size_t)tid * 16);
                cp16(dH + st_off1,        sH + (size_t)(tid + 256) * 16);
                cp16(dH + 9216 + st_off1, sL + (size_t)(tid + 256) * 16);
                CP_COMMIT();
            }

            // ---- HMMA: acc = Ah*Bh + Al*Bh + Ah*Bl (A frags in regs) ----
            const uint32_t bufb = smb + O_BUF + (uint32_t)((q & 1) * 18432);
            float acc[8][4];
            #pragma unroll
            for (int ct = 0; ct < 8; ct++)
                #pragma unroll
                for (int p = 0; p < 4; p++) acc[ct][p] = 0.f;
            #pragma unroll
            for (int ks = 0; ks < 4; ks++) {
                uint32_t bh[8][2];
                #pragma unroll
                for (int c2 = 0; c2 < 4; c2++) {
                    uint32_t bq[4];
                    ldb4(bq, bufb + (uint32_t)(c2 * 2304) + bRow4 + ks * 32);
                    bh[2*c2][0] = bq[0]; bh[2*c2][1] = bq[1];
                    bh[2*c2+1][0] = bq[2]; bh[2*c2+1][1] = bq[3];
                }
                #pragma unroll
                for (int ct = 0; ct < 8; ct++) mma16816(acc[ct], ah[ks], bh[ct]);
                #pragma unroll
                for (int ct = 0; ct < 8; ct++) mma16816(acc[ct], al[ks], bh[ct]);
                #pragma unroll
                for (int c2 = 0; c2 < 4; c2++) {
                    uint32_t bq[4];
                    ldb4(bq, bufb + 9216 + (uint32_t)(c2 * 2304) + bRow4 + ks * 32);
                    uint32_t bl0[2] = {bq[0], bq[1]}, bl1[2] = {bq[2], bq[3]};
                    mma16816(acc[2*c2],     ah[ks], bl0);
                    mma16816(acc[2*c2 + 1], ah[ks], bl1);
                }
            }

            // ---- phase B (registers): kl = ct>>1, j = (ct&1)*8+colq+{0,1} ----
            float4 x0 = make_float4(0.f, 0.f, 0.f, 0.f), x1 = x0;
            if (v0) x0 = *(const float4*)&src[(size_t)row0 * 64 + c * 16 + gg * 4];
            if (v1) x1 = *(const float4*)&src[(size_t)row1 * 64 + c * 16 + gg * 4];
            float xk0[4] = {x0.x, x0.y, x0.z, x0.w};
            float xk1[4] = {x1.x, x1.y, x1.z, x1.w};
            #pragma unroll
            for (int ct = 0; ct < 8; ct++) {
                float2 bb = *(const float2*)&b2s[c * 256 + gg * 64 + ct * 8 + colq];
                int kl = ct >> 1, jb = (ct & 1) * 2;
                y[jb]     = fmaf(xk0[kl], acc[ct][0] + bb.x, y[jb]);
                y[jb + 1] = fmaf(xk0[kl], acc[ct][1] + bb.y, y[jb + 1]);
                y[4 + jb]     = fmaf(xk1[kl], acc[ct][2] + bb.x, y[4 + jb]);
                y[4 + jb + 1] = fmaf(xk1[kl], acc[ct][3] + bb.y, y[4 + jb + 1]);
            }
        }

        if (!IS_K2) {
            if (v0) {
                *(float2*)&g_kyv[(size_t)row0 * 64 + c * 16 + colq]     = make_float2(y[0], y[1]);
                *(float2*)&g_kyv[(size_t)row0 * 64 + c * 16 + 8 + colq] = make_float2(y[2], y[3]);
            }
            if (v1) {
                *(float2*)&g_kyv[(size_t)row1 * 64 + c * 16 + colq]     = make_float2(y[4], y[5]);
                *(float2*)&g_kyv[(size_t)row1 * 64 + c * 16 + 8 + colq] = make_float2(y[6], y[7]);
            }
        } else {
            // v -> dead A smem region, pitch 68 floats (272B/row), mean folded
            char* vr0 = sm + r0 * 272 + (c * 16 + colq) * 4;
            char* vr1 = sm + (r0 + 8) * 272 + (c * 16 + colq) * 4;
            *(float2*)vr0        = make_float2(y[0] * inv0, y[1] * inv0);
            *(float2*)(vr0 + 32) = make_float2(y[2] * inv0, y[3] * inv0);
            *(float2*)vr1        = make_float2(y[4] * inv1, y[5] * inv1);
            *(float2*)(vr1 + 32) = make_float2(y[6] * inv1, y[7] * inv1);
        }
    }

    // ---- K2 tail: out = v @ mW^T + mb.  v in smem [0..34816), mW^T -> O_BUF.
    if (IS_K2) {
        __syncthreads();                           // v writes + B reads done
        #pragma unroll
        for (int it = 0; it < 16; it++) {
            int p = tid + it * 256;                // 4096
            int j = p >> 6, i = p & 63;
            *(float*)(sm + O_BUF + (j * 68 + i) * 4) = mW[(size_t)i * 64 + j];
        }
        __syncthreads();
        const int node_b = tid >> 1, jh = tid & 1;
        if (nb + node_b < n) {
            float a[32];
            #pragma unroll
            for (int p = 0; p < 8; p++) {
                float4 m4 = ((const float4*)mb)[jh * 8 + p];
                a[p*4] = m4.x; a[p*4+1] = m4.y; a[p*4+2] = m4.z; a[p*4+3] = m4.w;
            }
            #pragma unroll 4
            for (int j = 0; j < 64; j++) {
                float vj = *(const float*)(sm + (node_b * 68 + j) * 4);
                #pragma unroll
                for (int p = 0; p < 8; p++) {
                    float4 w = *(const float4*)(sm + O_BUF + (j * 68 + jh * 32 + p * 4) * 4);
                    a[p*4]   = fmaf(vj, w.x, a[p*4]);
                    a[p*4+1] = fmaf(vj, w.y, a[p*4+1]);
                    a[p*4+2] = fmaf(vj, w.z, a[p*4+2]);
                    a[p*4+3] = fmaf(vj, w.w, a[p*4+3]);
                }
            }
            float* dst = &out[(size_t)(nb + node_b) * 64 + jh * 32];
            #pragma unroll
            for (int p = 0; p < 8; p++)
                ((float4*)dst)[p] = make_float4(a[p*4], a[p*4+1], a[p*4+2], a[p*4+3]);
        }
    }
}

// ============================================================================
// Edge scatter: acc[dst] += ky_v[src], cnt[dst] += 1.  float4 vector atomics.
// ============================================================================
__global__ __launch_bounds__(256)
void scatter_kernel(const int* __restrict__ ei, int n_edges)
{
    __shared__ int s_dst[256];
    __shared__ int s_src[256];
    const int tid  = threadIdx.x;
    const int base = blockIdx.x * 256;
    const int nE   = min(256, n_edges - base);
    if (nE <= 0) return;

    if (tid < nE) {
        s_dst[tid] = ei[base + tid];
        s_src[tid] = ei[n_edges + base + tid];
    }
    __syncthreads();

    const int w = tid >> 5, lane = tid & 31;
    const int half16 = lane >> 4, l16 = lane & 15;

    #pragma unroll 4
    for (int p = 0; p < 16; p++) {
        int le = w * 32 + p * 2 + half16;
        if (le < nE) {
            int src = s_src[le];
            int dst = s_dst[le];
            float4 v = *(const float4*)&g_kyv[(size_t)src * 64 + l16 * 4];
            atomicAdd((float4*)&g_acc[(size_t)dst * 64 + l16 * 4], v);
            if (l16 == 0) atomicAdd(&g_cnt[dst], 1.0f);
        }
    }
}

// ============================================================================
extern "C" void kernel_launch(void* const* d_in, const int* in_sizes, int n_in,
                              void* d_out, int out_size)
{
    const float* x    = (const float*)d_in[0];
    const float* ea   = (const float*)d_in[1];
    const int*   ei   = (const int*)  d_in[2];
    const float* k1W1 = (const float*)d_in[3];
    const float* k1b1 = (const float*)d_in[4];
    const float* k1W2 = (const float*)d_in[5];
    const float* k1b2 = (const float*)d_in[6];
    const float* k2W1 = (const float*)d_in[7];
    const float* k2b1 = (const float*)d_in[8];
    const float* k2W2 = (const float*)d_in[9];
    const float* k2b2 = (const float*)d_in[10];
    const float* mW   = (const float*)d_in[11];
    const float* mb   = (const float*)d_in[12];
    float* out = (float*)d_out;

    const int n = in_sizes[0] / 64;        // 100000
    const int e = in_sizes[2] / 2;         // 3200000

    cudaFuncSetAttribute(node_kernel<0>, cudaFuncAttributeMaxDynamicSharedMemorySize, SMEM_SZ);
    cudaFuncSetAttribute(node_kernel<1>, cudaFuncAttributeMaxDynamicSharedMemorySize, SMEM_SZ);

    const int node_blocks = (n + TILE - 1) / TILE;
    const int edge_blocks = (e + 255) / 256;

    prep_kernel<<<32, 256>>>(k1W2, k2W2);
    node_kernel<0><<<node_blocks, 256, SMEM_SZ>>>(x, ea, k1W1, k1b1, k1b2,
                                                  nullptr, nullptr, nullptr, n);
    scatter_kernel<<<edge_blocks, 256>>>(ei, e);
    node_kernel<1><<<node_blocks, 256, SMEM_SZ>>>(nullptr, ea, k2W1, k2b1, k2b2,
                                                  mW, mb, out, n);
}

// round 10
// speedup vs baseline: 1.0718x; 1.0006x over previous
#include <cuda_runtime.h>
#include <cuda_bf16.h>
#include <cstdint>

#define NN   100000
#define TILE 128

// ---- scratch (allocation-free rule: __device__ globals) ----
__device__ float g_kyv[NN * 64];            // K1 output ky_v
__device__ float g_acc[NN * 64];            // scatter accumulator
__device__ float g_cnt[NN];                 // scatter counts
__device__ uint32_t g_Bhi[2][16][2048];     // prepacked W2 hi bf16 pairs [kid][c*4+g][col*32+m2]
__device__ uint32_t g_Blo[2][16][2048];     // prepacked W2 lo

// ============================================================================
// helpers
// ============================================================================
__device__ __forceinline__ uint32_t smem_u32(const void* p) {
    uint32_t a;
    asm("{ .reg .u64 t; cvta.to.shared.u64 t, %1; cvt.u32.u64 %0, t; }" : "=r"(a) : "l"(p));
    return a;
}
__device__ __forceinline__ void split_pack(float v0, float v1, uint32_t& hiw, uint32_t& low) {
    __nv_bfloat16 h0 = __float2bfloat16(v0), h1 = __float2bfloat16(v1);
    __nv_bfloat16 l0 = __float2bfloat16(v0 - __bfloat162float(h0));
    __nv_bfloat16 l1 = __float2bfloat16(v1 - __bfloat162float(h1));
    hiw = (uint32_t)__bfloat16_as_ushort(h0) | ((uint32_t)__bfloat16_as_ushort(h1) << 16);
    low = (uint32_t)__bfloat16_as_ushort(l0) | ((uint32_t)__bfloat16_as_ushort(l1) << 16);
}
__device__ __forceinline__ void lda4(uint32_t* r, uint32_t addr) {
    asm volatile("ldmatrix.sync.aligned.m8n8.x4.shared.b16 {%0,%1,%2,%3}, [%4];"
        : "=r"(r[0]), "=r"(r[1]), "=r"(r[2]), "=r"(r[3]) : "r"(addr));
}
__device__ __forceinline__ void ldb4(uint32_t* r, uint32_t addr) {
    asm volatile("ldmatrix.sync.aligned.m8n8.x4.shared.b16 {%0,%1,%2,%3}, [%4];"
        : "=r"(r[0]), "=r"(r[1]), "=r"(r[2]), "=r"(r[3]) : "r"(addr));
}
__device__ __forceinline__ void mma16816(float* c, const uint32_t* a, const uint32_t* b) {
    asm volatile("mma.sync.aligned.m16n8k16.row.col.f32.bf16.bf16.f32 "
        "{%0,%1,%2,%3}, {%4,%5,%6,%7}, {%8,%9}, {%0,%1,%2,%3};"
        : "+f"(c[0]), "+f"(c[1]), "+f"(c[2]), "+f"(c[3])
        : "r"(a[0]), "r"(a[1]), "r"(a[2]), "r"(a[3]), "r"(b[0]), "r"(b[1]));
}
__device__ __forceinline__ void cp16(uint32_t d, const void* s) {
    asm volatile("cp.async.ca.shared.global [%0], [%1], 16;" :: "r"(d), "l"(s));
}
#define CP_COMMIT() asm volatile("cp.async.commit_group;" ::: "memory")
#define CP_WAIT0()  asm volatile("cp.async.wait_group 0;"  ::: "memory")

// smem layout (bytes). A/B rows 144B (16B-aligned for ldmatrix; 144 mod 128 = 16
// -> conflict-free). After A-frag load, [0..34816) is dead: K2 stages v there
// (pitch 68 f32). Tail reuses O_BUF for mW^T (pitch 68 f32, 17408B).
enum { O_AHI = 0,                       // H hi : 128 x 144 = 18432
       O_ALO = 18432,                   // H lo : 128 x 144
       O_BUF = 36864,                   // 2 x (Bt hi 9216 + Bt lo 9216) = 36864
       O_B2  = 73728,                   // full b2: 1024 f32 = 4096
       SMEM_SZ = 77824 };

// ============================================================================
// prep: W2 -> bf16 hi/lo, ldmatrix tile layout [col][m2]. 32 blocks, ~5us.
// ============================================================================
__global__ __launch_bounds__(256)
void prep_kernel(const float* __restrict__ W2a, const float* __restrict__ W2b)
{
    const int b = blockIdx.x;              // 0..31
    const int k = b >> 4, t = b & 15;
    const int c = t >> 2, g = t & 3;
    const float* W2 = k ? W2b : W2a;
    const int tid = threadIdx.x;
    #pragma unroll
    for (int it = 0; it < 8; it++) {
        int p = tid + it * 256;            // 2048
        int col = p & 63, m2 = p >> 6;
        float w0 = W2[(size_t)(2 * m2)     * 1024 + c * 256 + g * 64 + col];
        float w1 = W2[(size_t)(2 * m2 + 1) * 1024 + c * 256 + g * 64 + col];
        uint32_t hi, lo;
        split_pack(w0, w1, hi, lo);
        g_Bhi[k][t][col * 32 + m2] = hi;
        g_Blo[k][t][col * 32 + m2] = lo;
    }
}

// ============================================================================
// Fused node kernel (round-8 structure + acc half-split).  A hi/lo frags in
// registers (loaded once, A smem dead after); B double-buffered via cp.async;
// ct tiles processed in two halves of 4 so acc is 16 live regs.
// K1 -> g_kyv (+zero acc/cnt).  K2: v -> dead A smem region, mix Linear tail.
// ============================================================================
template<int IS_K2>
__global__ __launch_bounds__(256, 2)
void node_kernel(const float* __restrict__ xin, const float* __restrict__ ea,
                 const float* __restrict__ W1, const float* __restrict__ b1,
                 const float* __restrict__ b2,
                 const float* __restrict__ mW, const float* __restrict__ mb,
                 float* __restrict__ out, int n)
{
    extern __shared__ __align__(16) char sm[];
    const uint32_t smb = smem_u32(sm);
    const int tid = threadIdx.x, wid = tid >> 5, lane = tid & 31;
    const int nb = blockIdx.x * TILE;

    // ---- stage A: h = relu(ea@W1+b1) hi/lo bf16, [node][m], row 144B ----
    {
        const int node = tid >> 1, mh = tid & 1;
        const bool ok = (nb + node) < n;
        float e0 = 0.f, e1 = 0.f, e2 = 0.f;
        if (ok) { const float* e = ea + (size_t)(nb + node) * 3; e0 = e[0]; e1 = e[1]; e2 = e[2]; }
        #pragma unroll
        for (int mm = 0; mm < 16; mm++) {
            int m = mh * 32 + mm * 2;
            float h0 = 0.f, h1 = 0.f;
            if (ok) {
                h0 = fmaxf(fmaf(e2, W1[128 + m],     fmaf(e1, W1[64 + m],     fmaf(e0, W1[m],     b1[m]))),     0.f);
                h1 = fmaxf(fmaf(e2, W1[128 + m + 1], fmaf(e1, W1[64 + m + 1], fmaf(e0, W1[m + 1], b1[m + 1]))), 0.f);
            }
            uint32_t hiw, low;
            split_pack(h0, h1, hiw, low);
            uint32_t off = (uint32_t)(node * 144 + m * 2);
            *(uint32_t*)(sm + O_AHI + off) = hiw;
            *(uint32_t*)(sm + O_ALO + off) = low;
        }
    }
    // ---- stage full b2 (1024 f32) once ----
    ((float4*)(sm + O_B2))[tid] = ((const float4*)b2)[tid];
    // ---- K1: zero scatter accumulators for this tile ----
    if (!IS_K2) {
        const float4 z4 = make_float4(0.f, 0.f, 0.f, 0.f);
        #pragma unroll
        for (int i = 0; i < 8; i++) {
            int idx4 = tid + i * 256;
            int node = idx4 >> 4;
            if (nb + node < n) ((float4*)g_acc)[(size_t)nb * 16 + idx4] = z4;
        }
        if (tid < TILE && nb + tid < n) g_cnt[nb + tid] = 0.f;
    }
    __syncthreads();                               // A + b2 staged

    // ---- load A fragments ONCE (A smem region dead afterwards) ----
    const uint32_t aRow = (uint32_t)((wid * 16 + (lane & 15)) * 144 + ((lane >> 4) * 16));
    uint32_t ah[4][4], al[4][4];
    #pragma unroll
    for (int ks = 0; ks < 4; ks++) {
        lda4(ah[ks], smb + O_AHI + aRow + ks * 32);
        lda4(al[ks], smb + O_ALO + aRow + ks * 32);
    }

    // x4 B addressing: lanes 16-31 take the next ct tile (+8 rows = +1152B)
    const uint32_t bRow4 = (uint32_t)((lane & 7) * 144 + (((lane >> 3) & 1) * 16)
                                      + ((lane >> 4) * 1152));
    const int r0   = wid * 16 + (lane >> 2);       // C frag rows r0, r0+8
    const int colq = 2 * (lane & 3);

    const int row0 = nb + r0, row1 = nb + r0 + 8;
    const bool v0 = row0 < n, v1 = row1 < n;
    const float* src = IS_K2 ? g_acc : xin;
    float inv0 = 1.f, inv1 = 1.f;
    if (IS_K2) {
        if (v0) inv0 = 1.0f / fmaxf(g_cnt[row0], 1.0f);
        if (v1) inv1 = 1.0f / fmaxf(g_cnt[row1], 1.0f);
    }

    // per-thread cp.async slots (same tile mapping as prep layout)
    const uint32_t st_off0 = (uint32_t)((tid >> 3) * 144 + (tid & 7) * 16);
    const uint32_t st_off1 = (uint32_t)(((tid + 256) >> 3) * 144 + (tid & 7) * 16);

    // ---- prologue: stage tile q=0 into buf 0 ----
    {
        const char* sH = (const char*)g_Bhi[IS_K2][0];
        const char* sL = (const char*)g_Blo[IS_K2][0];
        uint32_t dH = smb + O_BUF;
        cp16(dH + st_off0,        sH + (size_t)tid * 16);
        cp16(dH + 9216 + st_off0, sL + (size_t)tid * 16);
        cp16(dH + st_off1,        sH + (size_t)(tid + 256) * 16);
        cp16(dH + 9216 + st_off1, sL + (size_t)(tid + 256) * 16);
        CP_COMMIT();
    }

    const float* b2s = (const float*)(sm + O_B2);

    for (int c = 0; c < 4; c++) {
        float y[8] = {0.f, 0.f, 0.f, 0.f, 0.f, 0.f, 0.f, 0.f};

        for (int gg = 0; gg < 4; gg++) {
            const int q = c * 4 + gg;
            CP_WAIT0();
            __syncthreads();                       // buf q ready; buf q+1 free
            if (q < 15) {                          // async-stage next tile
                const char* sH = (const char*)g_Bhi[IS_K2][q + 1];
                const char* sL = (const char*)g_Blo[IS_K2][q + 1];
                uint32_t dH = smb + O_BUF + ((q + 1) & 1) * 18432;
                cp16(dH + st_off0,        sH + (size_t)tid * 16);
                cp16(dH + 9216 + st_off0, sL + (size_t)tid * 16);
                cp16(dH + st_off1,        sH + (size_t)(tid + 256) * 16);
                cp16(dH + 9216 + st_off1, sL + (size_t)(tid + 256) * 16);
                CP_COMMIT();
            }

            // x for phase B (load early; read-only data)
            float4 x0 = make_float4(0.f, 0.f, 0.f, 0.f), x1 = x0;
            if (v0) x0 = *(const float4*)&src[(size_t)row0 * 64 + c * 16 + gg * 4];
            if (v1) x1 = *(const float4*)&src[(size_t)row1 * 64 + c * 16 + gg * 4];
            float xk0a[4] = {x0.x, x0.y, x0.z, x0.w};
            float xk1a[4] = {x1.x, x1.y, x1.z, x1.w};

            const uint32_t bufb = smb + O_BUF + (uint32_t)((q & 1) * 18432);

            // ---- HMMA in two ct-halves (acc = 16 regs each) ----
            #pragma unroll
            for (int h = 0; h < 2; h++) {
                float acc[4][4];
                #pragma unroll
                for (int l = 0; l < 4; l++)
                    #pragma unroll
                    for (int p = 0; p < 4; p++) acc[l][p] = 0.f;
                #pragma unroll
                for (int ks = 0; ks < 4; ks++) {
                    #pragma unroll
                    for (int c2 = 0; c2 < 2; c2++) {
                        uint32_t bq[4];
                        ldb4(bq, bufb + (uint32_t)((h * 4 + c2 * 2) * 1152) + bRow4 + ks * 32);
                        mma16816(acc[c2 * 2],     ah[ks], bq);
                        mma16816(acc[c2 * 2 + 1], ah[ks], bq + 2);
                        mma16816(acc[c2 * 2],     al[ks], bq);
                        mma16816(acc[c2 * 2 + 1], al[ks], bq + 2);
                    }
                    #pragma unroll
                    for (int c2 = 0; c2 < 2; c2++) {
                        uint32_t bq[4];
                        ldb4(bq, bufb + 9216u + (uint32_t)((h * 4 + c2 * 2) * 1152) + bRow4 + ks * 32);
                        mma16816(acc[c2 * 2],     ah[ks], bq);
                        mma16816(acc[c2 * 2 + 1], ah[ks], bq + 2);
                    }
                }
                // ---- phase B for this half: round-8 formula with ct = h*4+l ----
                #pragma unroll
                for (int l = 0; l < 4; l++) {
                    const int ct = h * 4 + l;
                    const int kl = ct >> 1;
                    const int jb = (ct & 1) * 2;
                    float2 bb = *(const float2*)&b2s[c * 256 + gg * 64 + ct * 8 + colq];
                    y[jb]         = fmaf(xk0a[kl], acc[l][0] + bb.x, y[jb]);
                    y[jb + 1]     = fmaf(xk0a[kl], acc[l][1] + bb.y, y[jb + 1]);
                    y[4 + jb]     = fmaf(xk1a[kl], acc[l][2] + bb.x, y[4 + jb]);
                    y[4 + jb + 1] = fmaf(xk1a[kl], acc[l][3] + bb.y, y[4 + jb + 1]);
                }
            }
        }

        if (!IS_K2) {
            if (v0) {
                *(float2*)&g_kyv[(size_t)row0 * 64 + c * 16 + colq]     = make_float2(y[0], y[1]);
                *(float2*)&g_kyv[(size_t)row0 * 64 + c * 16 + 8 + colq] = make_float2(y[2], y[3]);
            }
            if (v1) {
                *(float2*)&g_kyv[(size_t)row1 * 64 + c * 16 + colq]     = make_float2(y[4], y[5]);
                *(float2*)&g_kyv[(size_t)row1 * 64 + c * 16 + 8 + colq] = make_float2(y[6], y[7]);
            }
        } else {
            // v -> dead A smem region, pitch 68 floats (272B/row), mean folded
            char* vr0 = sm + r0 * 272 + (c * 16 + colq) * 4;
            char* vr1 = sm + (r0 + 8) * 272 + (c * 16 + colq) * 4;
            *(float2*)vr0        = make_float2(y[0] * inv0, y[1] * inv0);
            *(float2*)(vr0 + 32) = make_float2(y[2] * inv0, y[3] * inv0);
            *(float2*)vr1        = make_float2(y[4] * inv1, y[5] * inv1);
            *(float2*)(vr1 + 32) = make_float2(y[6] * inv1, y[7] * inv1);
        }
    }

    // ---- K2 tail: out = v @ mW^T + mb.  v in smem [0..34816), mW^T -> O_BUF.
    if (IS_K2) {
        __syncthreads();                           // v writes + B reads done
        #pragma unroll
        for (int it = 0; it < 16; it++) {
            int p = tid + it * 256;                // 4096
            int j = p >> 6, i = p & 63;
            *(float*)(sm + O_BUF + (j * 68 + i) * 4) = mW[(size_t)i * 64 + j];
        }
        __syncthreads();
        const int node_b = tid >> 1, jh = tid & 1;
        if (nb + node_b < n) {
            float a[32];
            #pragma unroll
            for (int p = 0; p < 8; p++) {
                float4 m4 = ((const float4*)mb)[jh * 8 + p];
                a[p*4] = m4.x; a[p*4+1] = m4.y; a[p*4+2] = m4.z; a[p*4+3] = m4.w;
            }
            #pragma unroll 4
            for (int j = 0; j < 64; j++) {
                float vj = *(const float*)(sm + (node_b * 68 + j) * 4);
                #pragma unroll
                for (int p = 0; p < 8; p++) {
                    float4 w = *(const float4*)(sm + O_BUF + (j * 68 + jh * 32 + p * 4) * 4);
                    a[p*4]   = fmaf(vj, w.x, a[p*4]);
                    a[p*4+1] = fmaf(vj, w.y, a[p*4+1]);
                    a[p*4+2] = fmaf(vj, w.z, a[p*4+2]);
                    a[p*4+3] = fmaf(vj, w.w, a[p*4+3]);
                }
            }
            float* dst = &out[(size_t)(nb + node_b) * 64 + jh * 32];
            #pragma unroll
            for (int p = 0; p < 8; p++)
                ((float4*)dst)[p] = make_float4(a[p*4], a[p*4+1], a[p*4+2], a[p*4+3]);
        }
    }
}

// ============================================================================
// Edge scatter: acc[dst] += ky_v[src], cnt[dst] += 1.  float4 vector atomics.
// ============================================================================
__global__ __launch_bounds__(256)
void scatter_kernel(const int* __restrict__ ei, int n_edges)
{
    __shared__ int s_dst[256];
    __shared__ int s_src[256];
    const int tid  = threadIdx.x;
    const int base = blockIdx.x * 256;
    const int nE   = min(256, n_edges - base);
    if (nE <= 0) return;

    if (tid < nE) {
        s_dst[tid] = ei[base + tid];
        s_src[tid] = ei[n_edges + base + tid];
    }
    __syncthreads();

    const int w = tid >> 5, lane = tid & 31;
    const int half16 = lane >> 4, l16 = lane & 15;

    #pragma unroll 4
    for (int p = 0; p < 16; p++) {
        int le = w * 32 + p * 2 + half16;
        if (le < nE) {
            int src = s_src[le];
            int dst = s_dst[le];
            float4 v = *(const float4*)&g_kyv[(size_t)src * 64 + l16 * 4];
            atomicAdd((float4*)&g_acc[(size_t)dst * 64 + l16 * 4], v);
            if (l16 == 0) atomicAdd(&g_cnt[dst], 1.0f);
        }
    }
}

// ============================================================================
extern "C" void kernel_launch(void* const* d_in, const int* in_sizes, int n_in,
                              void* d_out, int out_size)
{
    const float* x    = (const float*)d_in[0];
    const float* ea   = (const float*)d_in[1];
    const int*   ei   = (const int*)  d_in[2];
    const float* k1W1 = (const float*)d_in[3];
    const float* k1b1 = (const float*)d_in[4];
    const float* k1W2 = (const float*)d_in[5];
    const float* k1b2 = (const float*)d_in[6];
    const float* k2W1 = (const float*)d_in[7];
    const float* k2b1 = (const float*)d_in[8];
    const float* k2W2 = (const float*)d_in[9];
    const float* k2b2 = (const float*)d_in[10];
    const float* mW   = (const float*)d_in[11];
    const float* mb   = (const float*)d_in[12];
    float* out = (float*)d_out;

    const int n = in_sizes[0] / 64;        // 100000
    const int e = in_sizes[2] / 2;         // 3200000

    cudaFuncSetAttribute(node_kernel<0>, cudaFuncAttributeMaxDynamicSharedMemorySize, SMEM_SZ);
    cudaFuncSetAttribute(node_kernel<1>, cudaFuncAttributeMaxDynamicSharedMemorySize, SMEM_SZ);

    const int node_blocks = (n + TILE - 1) / TILE;
    const int edge_blocks = (e + 255) / 256;

    prep_kernel<<<32, 256>>>(k1W2, k2W2);
    node_kernel<0><<<node_blocks, 256, SMEM_SZ>>>(x, ea, k1W1, k1b1, k1b2,
                                                  nullptr, nullptr, nullptr, n);
    scatter_kernel<<<edge_blocks, 256>>>(ei, e);
    node_kernel<1><<<node_blocks, 256, SMEM_SZ>>>(nullptr, ea, k2W1, k2b1, k2b2,
                                                  mW, mb, out, n);
}